// round 12
// baseline (speedup 1.0000x reference)
#include <cuda_runtime.h>
#include <cuda_bf16.h>
#include <math.h>

#define BB 2
#define TT 64
#define CC 384
#define HH 768
#define BKt 16
#define LDA_S 68
#define NB 288
#define KVN (128*768)   // 98304

// ---------------- scratch (device globals) ----------------
__device__ float g_parts[12*KVN];   // splitK parts, reused every stage (4.7MB)
__device__ float g_kvf[KVN];        // final k||v  [128][768]
__device__ float g_h1[KVN];         // final h1 pre-act (+bias) [128][768]
__device__ float g_dp[128*CC];      // final dp = p - v [128][384]
__device__ float g_ds[KVN];         // final ds [128][768]
__device__ float g_q[CC];
__device__ float g_h[BB*HH];
__device__ float g_pred[BB*CC];
__device__ unsigned g_cnt[128];     // per-tile arrival counters (monotonic)
__device__ unsigned g_bar[8];       // barrier tickets (monotonic)

__device__ __forceinline__ float silu_f(float x) {
    float s = 1.f / (1.f + expf(-x)); return x * s;
}
__device__ __forceinline__ float gfac_f(float x) {
    float s = 1.f / (1.f + expf(-x)); return s * (1.f + x * (1.f - s));
}

__device__ __forceinline__ void grid_bar(int which) {
    __syncthreads();
    if (threadIdx.x == 0) {
        unsigned* p = &g_bar[which];
        unsigned ticket;
        asm volatile("atom.release.gpu.global.add.u32 %0, [%1], 1;"
                     : "=r"(ticket) : "l"(p) : "memory");
        unsigned target = ticket - (ticket % NB) + NB;
        unsigned cur;
        do {
            __nanosleep(32);
            asm volatile("ld.acquire.gpu.global.u32 %0, [%1];"
                         : "=r"(cur) : "l"(p) : "memory");
        } while ((int)(cur - target) < 0);
    }
    __syncthreads();
}

__device__ __forceinline__ float warpdot4(const float4* a, const float4* b, int n4) {
    float s = 0.f;
    for (int i = (threadIdx.x & 31); i < n4; i += 32) {
        float4 x = a[i], y = b[i];
        s += x.x*y.x + x.y*y.y + x.z*y.z + x.w*y.w;
    }
    #pragma unroll
    for (int o = 16; o; o >>= 1) s += __shfl_xor_sync(0xFFFFFFFFu, s, o);
    return s;
}

__device__ __forceinline__ void core16(const float (*As)[LDA_S], const float (*Bs)[LDA_S],
                                       float (&acc)[4][4], int tm, int tn) {
    #pragma unroll
    for (int kk = 0; kk < BKt; ++kk) {
        float4 a4 = *(const float4*)&As[kk][tm*4];
        float4 b4 = *(const float4*)&Bs[kk][tn*4];
        float av[4] = {a4.x, a4.y, a4.z, a4.w};
        float bv[4] = {b4.x, b4.y, b4.z, b4.w};
        #pragma unroll
        for (int i = 0; i < 4; ++i)
            #pragma unroll
            for (int j = 0; j < 4; ++j)
                acc[i][j] += av[i] * bv[j];
    }
}

__device__ __forceinline__ void sts4(float (*S)[LDA_S], int r, int ks, float4 v) {
    S[ks+0][r] = v.x; S[ks+1][r] = v.y; S[ks+2][r] = v.z; S[ks+3][r] = v.w;
}

// sum npart parts at flat offset off (+q*4 cols); pstride = part size in floats
__device__ __forceinline__ void sum_tile(const float* base, size_t pstride, int npart,
                                         size_t off, float4 (&o)[4]) {
    o[0] = o[1] = o[2] = o[3] = make_float4(0.f, 0.f, 0.f, 0.f);
    for (int p = 0; p < npart; ++p) {
        const float* src = base + p*pstride + off;
        #pragma unroll
        for (int q = 0; q < 4; ++q) {
            float4 t = *(const float4*)(src + q*4);
            o[q].x += t.x; o[q].y += t.y; o[q].z += t.z; o[q].w += t.w;
        }
    }
}

// ============================================================================
__global__ void __launch_bounds__(256, 2)
fused(const float* __restrict__ x,   const float* __restrict__ Wq,
      const float* __restrict__ bq,  const float* __restrict__ Wk,
      const float* __restrict__ bk,  const float* __restrict__ Wv,
      const float* __restrict__ bv,  const float* __restrict__ Wo,
      const float* __restrict__ bo,  const float* __restrict__ iq,
      const float* __restrict__ sW0, const float* __restrict__ sb0,
      const float* __restrict__ sW1, const float* __restrict__ sb1,
      float* __restrict__ o_out, float* __restrict__ o_nw0,
      float* __restrict__ o_nb0, float* __restrict__ o_nw1,
      float* __restrict__ o_nb1)
{
    __shared__ float As[2][BKt][LDA_S];
    __shared__ float Bs[2][BKt][LDA_S];
    __shared__ float red[TT];
    __shared__ float coeff_s[TT];
    __shared__ int s_last;

    const int bid = blockIdx.x, tid = threadIdx.x;
    const int r  = tid >> 2, ks = (tid & 3) << 2;   // transpose-load role
    const int tm = tid & 15, tn = tid >> 4;          // micro-tile role
    const int rd_row = tid >> 2, rd_cb = (tid & 3) << 4;  // reducer role

    // ======== S1: kv GEMM all-288 (24 tiles x split12, K=32) + q dots ========
    {
        int kc = bid % 12, tile = bid / 12;
        int tr = tile / 12, tc = tile % 12;
        int m0 = tr*64, n0 = tc*64, k0 = kc*32;
        const float* Wn = (n0 < CC) ? Wk + (size_t)n0*CC : Wv + (size_t)(n0-CC)*CC;
        const float* pa = x  + (size_t)(m0 + r)*CC + k0 + ks;
        const float* pb = Wn + (size_t)r*CC       + k0 + ks;
        sts4(As[0], r, ks, *(const float4*)pa);
        sts4(Bs[0], r, ks, *(const float4*)pb);
        __syncthreads();
        float4 ra1 = *(const float4*)(pa + BKt), rb1 = *(const float4*)(pb + BKt);
        float acc[4][4] = {};
        core16(As[0], Bs[0], acc, tm, tn);
        sts4(As[1], r, ks, ra1); sts4(Bs[1], r, ks, rb1);
        __syncthreads();
        core16(As[1], Bs[1], acc, tm, tn);
        float* dst = g_parts + (size_t)kc*KVN;
        #pragma unroll
        for (int i = 0; i < 4; ++i)
            *(float4*)&dst[(size_t)(m0 + tm*4 + i)*768 + n0 + tn*4] =
                make_float4(acc[i][0], acc[i][1], acc[i][2], acc[i][3]);
        __syncthreads();
        if (tid == 0) {
            __threadfence();
            unsigned old = atomicAdd(&g_cnt[tile], 1u);
            s_last = ((old % 12u) == 11u);
        }
        __syncthreads();
        if (s_last) {
            __threadfence();
            int row = m0 + rd_row, cb = n0 + rd_cb;
            float4 o[4];
            sum_tile(g_parts, KVN, 12, (size_t)row*768 + cb, o);
            const float* bias = (cb < CC) ? bk + cb : bv + (cb - CC);
            #pragma unroll
            for (int q = 0; q < 4; ++q) {
                float4 b4 = *(const float4*)(bias + q*4);
                o[q].x += b4.x; o[q].y += b4.y; o[q].z += b4.z; o[q].w += b4.w;
                *(float4*)&g_kvf[(size_t)row*768 + cb + q*4] = o[q];
            }
        }
        if (bid < 48) {   // q: 384 dots K=384
            int w = bid*8 + (tid >> 5);
            float s = warpdot4((const float4*)iq, (const float4*)(Wq + (size_t)w*CC), CC/4);
            if ((tid & 31) == 0) g_q[w] = s + bq[w];
        }
    }
    grid_bar(0);

    // ======== S2: h1 GEMM all-288 (24 tiles x split12) + h dots ========
    {
        int kc = bid % 12, tile = bid / 12;
        int b = tile / 12, tc = tile % 12;
        int n0 = tc*64, k0 = kc*32;
        const float* pa = g_kvf + (size_t)(b*64 + r)*768 + k0 + ks;   // k cols
        const float* pb = sW0 + (size_t)(b*HH + n0 + r)*CC + k0 + ks;
        sts4(As[0], r, ks, *(const float4*)pa);
        sts4(Bs[0], r, ks, *(const float4*)pb);
        __syncthreads();
        float4 ra1 = *(const float4*)(pa + BKt), rb1 = *(const float4*)(pb + BKt);
        float acc[4][4] = {};
        core16(As[0], Bs[0], acc, tm, tn);
        sts4(As[1], r, ks, ra1); sts4(Bs[1], r, ks, rb1);
        __syncthreads();
        core16(As[1], Bs[1], acc, tm, tn);
        float* dst = g_parts + (size_t)kc*KVN;
        #pragma unroll
        for (int i = 0; i < 4; ++i)
            *(float4*)&dst[(size_t)(b*64 + tm*4 + i)*768 + n0 + tn*4] =
                make_float4(acc[i][0], acc[i][1], acc[i][2], acc[i][3]);
        __syncthreads();
        if (tid == 0) {
            __threadfence();
            unsigned old = atomicAdd(&g_cnt[32 + tile], 1u);
            s_last = ((old % 12u) == 11u);
        }
        __syncthreads();
        if (s_last) {
            __threadfence();
            int row = b*64 + rd_row, cb = n0 + rd_cb;
            float4 o[4];
            sum_tile(g_parts, KVN, 12, (size_t)row*768 + cb, o);
            #pragma unroll
            for (int q = 0; q < 4; ++q) {
                float4 b4 = *(const float4*)&sb0[b*HH + cb + q*4];
                o[q].x += b4.x; o[q].y += b4.y; o[q].z += b4.z; o[q].w += b4.w;
                *(float4*)&g_h1[(size_t)row*768 + cb + q*4] = o[q];
            }
        }
        if (bid >= 96) {  // h: 1536 dots K=384
            int w = (bid - 96)*8 + (tid >> 5);
            float s = warpdot4((const float4*)g_q, (const float4*)(sW0 + (size_t)w*CC),
                               CC/4) + sb0[w];
            if ((tid & 31) == 0) g_h[w] = silu_f(s);
        }
    }
    grid_bar(1);

    // ======== S3: p GEMM all-288 (12 tiles x split24), A=silu(h1) + pred dots ========
    {
        int kc = bid % 24, tile = bid / 24;
        int b = tile / 6, tc = tile % 6;
        int n0 = tc*64, k0 = kc*32;
        const float* pa = g_h1 + (size_t)(b*64 + r)*768 + k0 + ks;
        const float* pb = sW1 + (size_t)(b*CC + n0 + r)*HH + k0 + ks;
        float4 ra = *(const float4*)pa;
        sts4(As[0], r, ks, make_float4(silu_f(ra.x), silu_f(ra.y), silu_f(ra.z), silu_f(ra.w)));
        sts4(Bs[0], r, ks, *(const float4*)pb);
        __syncthreads();
        float4 ra1 = *(const float4*)(pa + BKt), rb1 = *(const float4*)(pb + BKt);
        float acc[4][4] = {};
        core16(As[0], Bs[0], acc, tm, tn);
        sts4(As[1], r, ks, make_float4(silu_f(ra1.x), silu_f(ra1.y), silu_f(ra1.z), silu_f(ra1.w)));
        sts4(Bs[1], r, ks, rb1);
        __syncthreads();
        core16(As[1], Bs[1], acc, tm, tn);
        float* dst = g_parts + (size_t)kc*(128*CC);
        #pragma unroll
        for (int i = 0; i < 4; ++i)
            *(float4*)&dst[(size_t)(b*64 + tm*4 + i)*CC + n0 + tn*4] =
                make_float4(acc[i][0], acc[i][1], acc[i][2], acc[i][3]);
        __syncthreads();
        if (tid == 0) {
            __threadfence();
            unsigned old = atomicAdd(&g_cnt[64 + tile], 1u);
            s_last = ((old % 24u) == 23u);
        }
        __syncthreads();
        if (s_last) {
            __threadfence();
            int row = b*64 + rd_row, cb = n0 + rd_cb;
            float4 o[4];
            sum_tile(g_parts, 128*CC, 24, (size_t)row*CC + cb, o);
            #pragma unroll
            for (int q = 0; q < 4; ++q) {
                float4 b4 = *(const float4*)&sb1[b*CC + cb + q*4];
                float4 v4 = *(const float4*)&g_kvf[(size_t)row*768 + 384 + cb + q*4];
                o[q].x += b4.x - v4.x; o[q].y += b4.y - v4.y;
                o[q].z += b4.z - v4.z; o[q].w += b4.w - v4.w;
                *(float4*)&g_dp[(size_t)row*CC + cb + q*4] = o[q];
            }
        }
        if (bid >= 96 && bid < 192) {  // pred: 768 dots K=768
            int w = (bid - 96)*8 + (tid >> 5);
            int b2 = w / CC;
            float s = warpdot4((const float4*)(g_h + b2*HH),
                               (const float4*)(sW1 + (size_t)w*HH), HH/4) + sb1[w];
            if ((tid & 31) == 0) g_pred[w] = s;
        }
    }
    grid_bar(2);

    // ======== S4: ds GEMM all-288 (24 tiles x split12, B NN) + out dots ========
    {
        int kc = bid % 12, tile = bid / 12;
        int b = tile / 12, tc = tile % 12;
        int n0 = tc*64, k0 = kc*32;
        int kkb = tid >> 4, cs = (tid & 15) << 2;
        const float* pa = g_dp + (size_t)(b*64 + r)*CC + k0 + ks;
        const float* pb = sW1 + (size_t)(b*CC + k0 + kkb)*HH + n0 + cs;
        sts4(As[0], r, ks, *(const float4*)pa);
        *(float4*)&Bs[0][kkb][cs] = *(const float4*)pb;
        __syncthreads();
        float4 ra1 = *(const float4*)(pa + BKt);
        float4 rb1 = *(const float4*)(pb + (size_t)BKt*HH);
        float acc[4][4] = {};
        core16(As[0], Bs[0], acc, tm, tn);
        sts4(As[1], r, ks, ra1);
        *(float4*)&Bs[1][kkb][cs] = rb1;
        __syncthreads();
        core16(As[1], Bs[1], acc, tm, tn);
        float* dst = g_parts + (size_t)kc*KVN;
        #pragma unroll
        for (int i = 0; i < 4; ++i)
            *(float4*)&dst[(size_t)(b*64 + tm*4 + i)*768 + n0 + tn*4] =
                make_float4(acc[i][0], acc[i][1], acc[i][2], acc[i][3]);
        __syncthreads();
        if (tid == 0) {
            __threadfence();
            unsigned old = atomicAdd(&g_cnt[96 + tile], 1u);
            s_last = ((old % 12u) == 11u);
        }
        __syncthreads();
        if (s_last) {
            __threadfence();
            int row = b*64 + rd_row, cb = n0 + rd_cb;
            float4 o[4];
            sum_tile(g_parts, KVN, 12, (size_t)row*768 + cb, o);
            #pragma unroll
            for (int q = 0; q < 4; ++q)
                *(float4*)&g_ds[(size_t)row*768 + cb + q*4] = o[q];
        }
        if (bid >= 192) {  // out: 768 dots K=384
            int w = (bid - 192)*8 + (tid >> 5);
            int b2 = w / CC, c = w % CC;
            float s = warpdot4((const float4*)(g_pred + b2*CC),
                               (const float4*)(Wo + (size_t)c*CC), CC/4) + bo[c];
            if ((tid & 31) == 0) o_out[w] = s;
        }
    }
    grid_bar(3);

    // ======== S5: nW0 (144) + nW1 (144), biases folded into tc==0 tiles ========
    {
        if (tid < TT) {
            double d = 0.999, rr_ = 0.9 / 0.999;
            double csm = pow(d, (double)(TT-1-tid)) * (pow(rr_, (double)(TT-tid)) - 1.0)
                         / (rr_ - 1.0);
            coeff_s[tid] = (float)(-0.01 * 0.1 * csm);
        }
        __syncthreads();
        const float df = (float)pow(0.999, (double)TT);

        bool is0 = bid < 144;
        int tile = is0 ? bid : bid - 144;
        int bb = tile / 72, rr = tile % 72;
        int tr = is0 ? rr/6 : rr/12;
        int tc = is0 ? rr%6 : rr%12;
        int m0 = tr*64, n0 = tc*64;
        int kk = tid >> 4, ms = (tid & 15) << 2;
        float4 r1, r2, r3;
        float csum[4] = {0.f, 0.f, 0.f, 0.f};

        #define LD_SLAB(kt) do {                                                   \
            int t_ = (kt)*BKt + kk;                                                \
            if (is0) {                                                             \
                size_t ia = (size_t)(bb*TT + t_)*768 + m0 + ms;                    \
                r1 = *(const float4*)&g_ds[ia];                                    \
                r2 = *(const float4*)&g_h1[ia];                                    \
                r3 = *(const float4*)&g_kvf[(size_t)(bb*TT + t_)*768 + n0 + ms];   \
            } else {                                                               \
                r1 = *(const float4*)&g_dp[(size_t)(bb*TT + t_)*CC + m0 + ms];     \
                r2 = *(const float4*)&g_h1[(size_t)(bb*TT + t_)*768 + n0 + ms];    \
            }                                                                      \
        } while (0)
        #define ST_SLAB(buf, kt) do {                                              \
            int t_ = (kt)*BKt + kk;                                                \
            float cf = coeff_s[t_];                                                \
            float a0, a1, a2, a3;                                                  \
            if (is0) {                                                             \
                a0 = cf * r1.x * gfac_f(r2.x); a1 = cf * r1.y * gfac_f(r2.y);      \
                a2 = cf * r1.z * gfac_f(r2.z); a3 = cf * r1.w * gfac_f(r2.w);      \
                *(float4*)&Bs[buf][kk][ms] = r3;                                   \
            } else {                                                               \
                a0 = cf * r1.x; a1 = cf * r1.y; a2 = cf * r1.z; a3 = cf * r1.w;    \
                Bs[buf][kk][ms+0] = silu_f(r2.x); Bs[buf][kk][ms+1] = silu_f(r2.y);\
                Bs[buf][kk][ms+2] = silu_f(r2.z); Bs[buf][kk][ms+3] = silu_f(r2.w);\
            }                                                                      \
            As[buf][kk][ms+0] = a0; As[buf][kk][ms+1] = a1;                        \
            As[buf][kk][ms+2] = a2; As[buf][kk][ms+3] = a3;                        \
            csum[0] += a0; csum[1] += a1; csum[2] += a2; csum[3] += a3;            \
        } while (0)

        LD_SLAB(0); ST_SLAB(0, 0);
        __syncthreads();
        float acc[4][4] = {};
        #pragma unroll
        for (int kt = 0; kt < 4; ++kt) {
            if (kt < 3) LD_SLAB(kt+1);
            core16(As[kt&1], Bs[kt&1], acc, tm, tn);
            if (kt < 3) ST_SLAB((kt+1)&1, kt+1);
            __syncthreads();
        }
        if (is0) {
            #pragma unroll
            for (int i = 0; i < 4; ++i) {
                int h = m0 + tm*4 + i;
                #pragma unroll
                for (int j = 0; j < 4; ++j) {
                    size_t idx = (size_t)(bb*HH + h)*CC + n0 + tn*4 + j;
                    o_nw0[idx] = df * sW0[idx] + acc[i][j];
                }
            }
        } else {
            #pragma unroll
            for (int i = 0; i < 4; ++i) {
                int c = m0 + tm*4 + i;
                #pragma unroll
                for (int j = 0; j < 4; ++j) {
                    size_t idx = (size_t)(bb*CC + c)*HH + n0 + tn*4 + j;
                    o_nw1[idx] = df * sW1[idx] + acc[i][j];
                }
            }
        }
        if (tc == 0) {   // fold biases: column sums of A
            if (tid < TT) red[tid] = 0.f;
            __syncthreads();
            atomicAdd(&red[ms+0], csum[0]); atomicAdd(&red[ms+1], csum[1]);
            atomicAdd(&red[ms+2], csum[2]); atomicAdd(&red[ms+3], csum[3]);
            __syncthreads();
            if (tid < TT) {
                if (is0) o_nb0[bb*HH + m0 + tid] = df * sb0[bb*HH + m0 + tid] + red[tid];
                else     o_nb1[bb*CC + m0 + tid] = df * sb1[bb*CC + m0 + tid] + red[tid];
            }
        }
    }
}

// ============================================================================
extern "C" void kernel_launch(void* const* d_in, const int* in_sizes, int n_in,
                              void* d_out, int out_size) {
    const float* x   = (const float*)d_in[0];
    const float* Wq  = (const float*)d_in[1];
    const float* bq  = (const float*)d_in[2];
    const float* Wk  = (const float*)d_in[3];
    const float* bk  = (const float*)d_in[4];
    const float* Wv  = (const float*)d_in[5];
    const float* bv  = (const float*)d_in[6];
    const float* Wo  = (const float*)d_in[7];
    const float* bo  = (const float*)d_in[8];
    const float* iq  = (const float*)d_in[9];
    const float* sW0 = (const float*)d_in[10];
    const float* sb0 = (const float*)d_in[11];
    const float* sW1 = (const float*)d_in[12];
    const float* sb1 = (const float*)d_in[13];

    float* out   = (float*)d_out;
    float* o_out = out;
    float* o_nw0 = o_out + BB*CC;
    float* o_nb0 = o_nw0 + (size_t)BB*HH*CC;
    float* o_nw1 = o_nb0 + BB*HH;
    float* o_nb1 = o_nw1 + (size_t)BB*CC*HH;

    fused<<<NB, 256>>>(x, Wq, bq, Wk, bk, Wv, bv, Wo, bo, iq, sW0, sb0, sW1, sb1,
                       o_out, o_nw0, o_nb0, o_nw1, o_nb1);
}

// round 13
// speedup vs baseline: 1.3653x; 1.3653x over previous
#include <cuda_runtime.h>
#include <cuda_bf16.h>
#include <math.h>

#define BB 2
#define TT 64
#define CC 384
#define HH 768
#define BKt 16
#define LDA_S 68
#define NB 288
#define RNK (128*768)   // 98304
#define RNC (128*384)   // 49152

// ---------------- scratch (device globals) ----------------
__device__ float g_kvp[6*RNK];   // k||v parts (bias baked into part 0)
__device__ float g_h1p[6*RNK];   // h1 pre-act parts (sb0 baked into part 0)
__device__ float g_dpp[6*RNC];   // dp parts (sb1 - v baked into part 0)
__device__ float g_dsp[6*RNK];   // ds parts
__device__ float g_k[RNC];       // finalized k   [128][384]
__device__ float g_v[RNC];       // finalized v   [128][384]
__device__ float g_h1[RNK];      // finalized h1 pre-act [128][768]
__device__ float g_q[CC];
__device__ float g_h[BB*HH];
__device__ float g_pred[BB*CC];
__device__ unsigned g_bar[8];    // monotonic barrier tickets

__device__ __forceinline__ float silu_f(float x) {
    float s = 1.f / (1.f + expf(-x)); return x * s;
}
__device__ __forceinline__ float gfac_f(float x) {
    float s = 1.f / (1.f + expf(-x)); return s * (1.f + x * (1.f - s));
}

__device__ __forceinline__ void grid_bar(int which) {
    __syncthreads();
    if (threadIdx.x == 0) {
        unsigned* p = &g_bar[which];
        unsigned ticket;
        asm volatile("atom.release.gpu.global.add.u32 %0, [%1], 1;"
                     : "=r"(ticket) : "l"(p) : "memory");
        unsigned target = ticket - (ticket % NB) + NB;
        unsigned cur;
        do {
            __nanosleep(32);
            asm volatile("ld.acquire.gpu.global.u32 %0, [%1];"
                         : "=r"(cur) : "l"(p) : "memory");
        } while ((int)(cur - target) < 0);
    }
    __syncthreads();
}

__device__ __forceinline__ float warpdot4(const float4* a, const float4* b, int n4) {
    float s = 0.f;
    for (int i = (threadIdx.x & 31); i < n4; i += 32) {
        float4 x = a[i], y = b[i];
        s += x.x*y.x + x.y*y.y + x.z*y.z + x.w*y.w;
    }
    #pragma unroll
    for (int o = 16; o; o >>= 1) s += __shfl_xor_sync(0xFFFFFFFFu, s, o);
    return s;
}

__device__ __forceinline__ void core16(const float (*As)[LDA_S], const float (*Bs)[LDA_S],
                                       float (&acc)[4][4], int tm, int tn) {
    #pragma unroll
    for (int kk = 0; kk < BKt; ++kk) {
        float4 a4 = *(const float4*)&As[kk][tm*4];
        float4 b4 = *(const float4*)&Bs[kk][tn*4];
        float av[4] = {a4.x, a4.y, a4.z, a4.w};
        float bv[4] = {b4.x, b4.y, b4.z, b4.w};
        #pragma unroll
        for (int i = 0; i < 4; ++i)
            #pragma unroll
            for (int j = 0; j < 4; ++j)
                acc[i][j] += av[i] * bv[j];
    }
}

__device__ __forceinline__ void sts4(float (*S)[LDA_S], int r, int ks, float4 v) {
    S[ks+0][r] = v.x; S[ks+1][r] = v.y; S[ks+2][r] = v.z; S[ks+3][r] = v.w;
}

__device__ __forceinline__ float4 sum6(const float* base, size_t pstride, size_t off) {
    float4 s = make_float4(0.f, 0.f, 0.f, 0.f);
    #pragma unroll
    for (int p = 0; p < 6; ++p) {
        float4 t = *(const float4*)(base + (size_t)p*pstride + off);
        s.x += t.x; s.y += t.y; s.z += t.z; s.w += t.w;
    }
    return s;
}

// ============================================================================
__global__ void __launch_bounds__(256, 2)
fused(const float* __restrict__ x,   const float* __restrict__ Wq,
      const float* __restrict__ bq,  const float* __restrict__ Wk,
      const float* __restrict__ bk,  const float* __restrict__ Wv,
      const float* __restrict__ bv,  const float* __restrict__ Wo,
      const float* __restrict__ bo,  const float* __restrict__ iq,
      const float* __restrict__ sW0, const float* __restrict__ sb0,
      const float* __restrict__ sW1, const float* __restrict__ sb1,
      float* __restrict__ o_out, float* __restrict__ o_nw0,
      float* __restrict__ o_nb0, float* __restrict__ o_nw1,
      float* __restrict__ o_nb1)
{
    __shared__ float As[2][BKt][LDA_S];
    __shared__ float Bs[2][BKt][LDA_S];
    __shared__ float red[TT];
    __shared__ float coeff_s[TT];

    const int bid = blockIdx.x, tid = threadIdx.x;
    const int r  = tid >> 2, ks = (tid & 3) << 2;   // transpose-load role
    const int tm = tid & 15, tn = tid >> 4;          // micro-tile role

    // coeff / decay factor (once, up front; used in S4/S5)
    if (tid < TT) {
        double d = 0.999, rr_ = 0.9 / 0.999;
        double csm = pow(d, (double)(TT-1-tid)) * (pow(rr_, (double)(TT-tid)) - 1.0)
                     / (rr_ - 1.0);
        coeff_s[tid] = (float)(-0.01 * 0.1 * csm);
    }
    const float df = (float)pow(0.999, (double)TT);
    __syncthreads();

    // ======== S1: kv GEMM parts (144) | q dots (48) ========
    if (bid < 144) {
        int kc = bid % 6, tile = bid / 6;
        int tr = tile / 12, tc = tile % 12;
        int m0 = tr*64, n0 = tc*64, k0 = kc*64;
        const float* Wn = (n0 < CC) ? Wk + (size_t)n0*CC : Wv + (size_t)(n0-CC)*CC;
        const float* pa = x  + (size_t)(m0 + r)*CC + k0 + ks;
        const float* pb = Wn + (size_t)r*CC       + k0 + ks;
        sts4(As[0], r, ks, *(const float4*)pa);
        sts4(Bs[0], r, ks, *(const float4*)pb);
        __syncthreads();
        float acc[4][4] = {};
        #pragma unroll
        for (int kt = 0; kt < 4; ++kt) {
            float4 ra, rb;
            if (kt < 3) { ra = *(const float4*)(pa + (kt+1)*BKt);
                          rb = *(const float4*)(pb + (kt+1)*BKt); }
            core16(As[kt&1], Bs[kt&1], acc, tm, tn);
            if (kt < 3) { sts4(As[(kt+1)&1], r, ks, ra); sts4(Bs[(kt+1)&1], r, ks, rb); }
            __syncthreads();
        }
        float4 badd = make_float4(0.f, 0.f, 0.f, 0.f);
        if (kc == 0) {
            int c = n0 + tn*4;
            const float* bsrc = (c < CC) ? bk + c : bv + (c - CC);
            badd = make_float4(bsrc[0], bsrc[1], bsrc[2], bsrc[3]);
        }
        float* dst = g_kvp + (size_t)kc*RNK;
        #pragma unroll
        for (int i = 0; i < 4; ++i)
            *(float4*)&dst[(size_t)(m0 + tm*4 + i)*768 + n0 + tn*4] =
                make_float4(acc[i][0]+badd.x, acc[i][1]+badd.y,
                            acc[i][2]+badd.z, acc[i][3]+badd.w);
    } else if (bid < 192) {   // q: 384 dots K=384
        int w = (bid - 144)*8 + (tid >> 5);
        float s = warpdot4((const float4*)iq, (const float4*)(Wq + (size_t)w*CC), CC/4);
        if ((tid & 31) == 0) g_q[w] = s + bq[w];
    }
    grid_bar(0);

    // ======== S2: h1 GEMM parts (144, A=sum6 kvp) | finalize k,v + h dots ========
    if (bid < 144) {
        int kc = bid % 6, tile = bid / 6;
        int b = tile / 12, tc = tile % 12;
        int n0 = tc*64, k0 = kc*64;
        size_t abase = (size_t)(b*64 + r)*768 + k0 + ks;
        const float* pb = sW0 + (size_t)(b*HH + n0 + r)*CC + k0 + ks;
        sts4(As[0], r, ks, sum6(g_kvp, RNK, abase));
        sts4(Bs[0], r, ks, *(const float4*)pb);
        __syncthreads();
        float acc[4][4] = {};
        #pragma unroll
        for (int kt = 0; kt < 4; ++kt) {
            float4 ra, rb;
            if (kt < 3) { ra = sum6(g_kvp, RNK, abase + (kt+1)*BKt);
                          rb = *(const float4*)(pb + (kt+1)*BKt); }
            core16(As[kt&1], Bs[kt&1], acc, tm, tn);
            if (kt < 3) { sts4(As[(kt+1)&1], r, ks, ra); sts4(Bs[(kt+1)&1], r, ks, rb); }
            __syncthreads();
        }
        float4 badd = make_float4(0.f, 0.f, 0.f, 0.f);
        if (kc == 0) {
            const float* bsrc = sb0 + b*HH + n0 + tn*4;
            badd = make_float4(bsrc[0], bsrc[1], bsrc[2], bsrc[3]);
        }
        float* dst = g_h1p + (size_t)kc*RNK;
        #pragma unroll
        for (int i = 0; i < 4; ++i)
            *(float4*)&dst[(size_t)(b*64 + tm*4 + i)*768 + n0 + tn*4] =
                make_float4(acc[i][0]+badd.x, acc[i][1]+badd.y,
                            acc[i][2]+badd.z, acc[i][3]+badd.w);
    } else {
        int gt = (bid - 144)*256 + tid;
        if (gt < RNC/4) {            // finalize k, v
            int row = gt / 96, c4 = (gt % 96) * 4;
            *(float4*)&g_k[(size_t)row*CC + c4] = sum6(g_kvp, RNK, (size_t)row*768 + c4);
            *(float4*)&g_v[(size_t)row*CC + c4] = sum6(g_kvp, RNK, (size_t)row*768 + 384 + c4);
        }
        for (int w = (bid - 144)*8 + (tid >> 5); w < BB*HH; w += 144*8) {  // h dots
            float s = warpdot4((const float4*)g_q, (const float4*)(sW0 + (size_t)w*CC),
                               CC/4) + sb0[w];
            if ((tid & 31) == 0) g_h[w] = silu_f(s);
        }
    }
    grid_bar(1);

    // ======== S3: dp GEMM parts (72, K=128, A=silu(sum6 h1p)) | finalize h1 + pred ========
    if (bid < 72) {
        int kc = bid % 6, tile = bid / 6;
        int b = tile / 6, tc = tile % 6;
        int n0 = tc*64, k0 = kc*128;
        size_t abase = (size_t)(b*64 + r)*768 + k0 + ks;
        const float* pb = sW1 + (size_t)(b*CC + n0 + r)*HH + k0 + ks;
        {
            float4 a0 = sum6(g_h1p, RNK, abase);
            sts4(As[0], r, ks, make_float4(silu_f(a0.x), silu_f(a0.y),
                                           silu_f(a0.z), silu_f(a0.w)));
        }
        sts4(Bs[0], r, ks, *(const float4*)pb);
        __syncthreads();
        float acc[4][4] = {};
        #pragma unroll
        for (int kt = 0; kt < 8; ++kt) {
            float4 ra, rb;
            if (kt < 7) { ra = sum6(g_h1p, RNK, abase + (kt+1)*BKt);
                          rb = *(const float4*)(pb + (kt+1)*BKt); }
            core16(As[kt&1], Bs[kt&1], acc, tm, tn);
            if (kt < 7) {
                sts4(As[(kt+1)&1], r, ks, make_float4(silu_f(ra.x), silu_f(ra.y),
                                                      silu_f(ra.z), silu_f(ra.w)));
                sts4(Bs[(kt+1)&1], r, ks, rb);
            }
            __syncthreads();
        }
        float* dst = g_dpp + (size_t)kc*RNC;
        #pragma unroll
        for (int i = 0; i < 4; ++i) {
            int m = b*64 + tm*4 + i;
            int c = n0 + tn*4;
            float4 badd = make_float4(0.f, 0.f, 0.f, 0.f);
            if (kc == 0) {
                float4 v4 = *(const float4*)&g_v[(size_t)m*CC + c];
                const float* bsrc = sb1 + b*CC + c;
                badd = make_float4(bsrc[0]-v4.x, bsrc[1]-v4.y, bsrc[2]-v4.z, bsrc[3]-v4.w);
            }
            *(float4*)&dst[(size_t)m*CC + c] =
                make_float4(acc[i][0]+badd.x, acc[i][1]+badd.y,
                            acc[i][2]+badd.z, acc[i][3]+badd.w);
        }
    } else {
        int gt = (bid - 72)*256 + tid;
        if (gt < RNK/4)              // finalize h1 (pre-act incl bias)
            *(float4*)&g_h1[(size_t)gt*4] = sum6(g_h1p, RNK, (size_t)gt*4);
        if (bid < 168) {             // pred: 768 dots K=768
            int w = (bid - 72)*8 + (tid >> 5);
            int b2 = w / CC;
            float s = warpdot4((const float4*)(g_h + b2*HH),
                               (const float4*)(sW1 + (size_t)w*HH), HH/4) + sb1[w];
            if ((tid & 31) == 0) g_pred[w] = s;
        }
    }
    grid_bar(2);

    // ======== S4: ds GEMM parts (144, A=sum6 dpp) | nW1 GEMM (144) + nb1 ========
    if (bid < 144) {
        int kc = bid % 6, tile = bid / 6;
        int b = tile / 12, tc = tile % 12;
        int n0 = tc*64, k0 = kc*64;
        int kkb = tid >> 4, cs = (tid & 15) << 2;
        size_t abase = (size_t)(b*64 + r)*CC + k0 + ks;
        const float* pb = sW1 + (size_t)(b*CC + k0 + kkb)*HH + n0 + cs;
        sts4(As[0], r, ks, sum6(g_dpp, RNC, abase));
        *(float4*)&Bs[0][kkb][cs] = *(const float4*)pb;
        __syncthreads();
        float acc[4][4] = {};
        #pragma unroll
        for (int kt = 0; kt < 4; ++kt) {
            float4 ra, rb;
            if (kt < 3) { ra = sum6(g_dpp, RNC, abase + (kt+1)*BKt);
                          rb = *(const float4*)(pb + (size_t)(kt+1)*BKt*HH); }
            core16(As[kt&1], Bs[kt&1], acc, tm, tn);
            if (kt < 3) { sts4(As[(kt+1)&1], r, ks, ra);
                          *(float4*)&Bs[(kt+1)&1][kkb][cs] = rb; }
            __syncthreads();
        }
        float* dst = g_dsp + (size_t)kc*RNK;
        #pragma unroll
        for (int i = 0; i < 4; ++i)
            *(float4*)&dst[(size_t)(b*64 + tm*4 + i)*768 + n0 + tn*4] =
                make_float4(acc[i][0], acc[i][1], acc[i][2], acc[i][3]);
    } else {
        // nW1: A[t][c] = coeff*dp (sum6 dpp), B[t][h] = silu(g_h1)
        int tile = bid - 144;
        int bb = tile / 72, rr = tile % 72;
        int tr = rr / 12, tc = rr % 12;
        int m0 = tr*64, n0 = tc*64;
        int kk = tid >> 4, ms = (tid & 15) << 2;
        float csum[4] = {0.f, 0.f, 0.f, 0.f};
        float4 r1, r2;
        #define NW1_LD(kt) do {                                                    \
            int t_ = (kt)*BKt + kk;                                                \
            r1 = sum6(g_dpp, RNC, (size_t)(bb*64 + t_)*CC + m0 + ms);              \
            r2 = *(const float4*)&g_h1[(size_t)(bb*64 + t_)*768 + n0 + ms];        \
        } while (0)
        #define NW1_ST(buf, kt) do {                                               \
            int t_ = (kt)*BKt + kk;                                                \
            float cf = coeff_s[t_];                                                \
            float a0 = cf*r1.x, a1 = cf*r1.y, a2 = cf*r1.z, a3 = cf*r1.w;          \
            As[buf][kk][ms+0] = a0; As[buf][kk][ms+1] = a1;                        \
            As[buf][kk][ms+2] = a2; As[buf][kk][ms+3] = a3;                        \
            Bs[buf][kk][ms+0] = silu_f(r2.x); Bs[buf][kk][ms+1] = silu_f(r2.y);    \
            Bs[buf][kk][ms+2] = silu_f(r2.z); Bs[buf][kk][ms+3] = silu_f(r2.w);    \
            csum[0] += a0; csum[1] += a1; csum[2] += a2; csum[3] += a3;            \
        } while (0)
        NW1_LD(0); NW1_ST(0, 0);
        __syncthreads();
        float acc[4][4] = {};
        #pragma unroll
        for (int kt = 0; kt < 4; ++kt) {
            if (kt < 3) NW1_LD(kt+1);
            core16(As[kt&1], Bs[kt&1], acc, tm, tn);
            if (kt < 3) NW1_ST((kt+1)&1, kt+1);
            __syncthreads();
        }
        #pragma unroll
        for (int i = 0; i < 4; ++i) {
            int c = m0 + tm*4 + i;
            #pragma unroll
            for (int j = 0; j < 4; ++j) {
                size_t idx = (size_t)(bb*CC + c)*HH + n0 + tn*4 + j;
                o_nw1[idx] = df * sW1[idx] + acc[i][j];
            }
        }
        if (tc == 0) {
            if (tid < TT) red[tid] = 0.f;
            __syncthreads();
            atomicAdd(&red[ms+0], csum[0]); atomicAdd(&red[ms+1], csum[1]);
            atomicAdd(&red[ms+2], csum[2]); atomicAdd(&red[ms+3], csum[3]);
            __syncthreads();
            if (tid < TT)
                o_nb1[bb*CC + m0 + tid] = df * sb1[bb*CC + m0 + tid] + red[tid];
        }
    }
    grid_bar(3);

    // ======== S5: nW0 (144) + nb0 | out dots (96) ========
    if (bid < 144) {
        int bb = bid / 72, rr = bid % 72;
        int tr = rr / 6, tc = rr % 6;
        int m0 = tr*64, n0 = tc*64;
        int kk = tid >> 4, ms = (tid & 15) << 2;
        float csum[4] = {0.f, 0.f, 0.f, 0.f};
        float4 r1, r2, r3;
        #define NW0_LD(kt) do {                                                    \
            int t_ = (kt)*BKt + kk;                                                \
            size_t ia = (size_t)(bb*64 + t_)*768 + m0 + ms;                        \
            r1 = sum6(g_dsp, RNK, ia);                                             \
            r2 = *(const float4*)&g_h1[ia];                                        \
            r3 = *(const float4*)&g_k[(size_t)(bb*64 + t_)*CC + n0 + ms];          \
        } while (0)
        #define NW0_ST(buf, kt) do {                                               \
            int t_ = (kt)*BKt + kk;                                                \
            float cf = coeff_s[t_];                                                \
            float a0 = cf*r1.x*gfac_f(r2.x), a1 = cf*r1.y*gfac_f(r2.y);            \
            float a2 = cf*r1.z*gfac_f(r2.z), a3 = cf*r1.w*gfac_f(r2.w);            \
            As[buf][kk][ms+0] = a0; As[buf][kk][ms+1] = a1;                        \
            As[buf][kk][ms+2] = a2; As[buf][kk][ms+3] = a3;                        \
            *(float4*)&Bs[buf][kk][ms] = r3;                                       \
            csum[0] += a0; csum[1] += a1; csum[2] += a2; csum[3] += a3;            \
        } while (0)
        NW0_LD(0); NW0_ST(0, 0);
        __syncthreads();
        float acc[4][4] = {};
        #pragma unroll
        for (int kt = 0; kt < 4; ++kt) {
            if (kt < 3) NW0_LD(kt+1);
            core16(As[kt&1], Bs[kt&1], acc, tm, tn);
            if (kt < 3) NW0_ST((kt+1)&1, kt+1);
            __syncthreads();
        }
        #pragma unroll
        for (int i = 0; i < 4; ++i) {
            int h = m0 + tm*4 + i;
            #pragma unroll
            for (int j = 0; j < 4; ++j) {
                size_t idx = (size_t)(bb*HH + h)*CC + n0 + tn*4 + j;
                o_nw0[idx] = df * sW0[idx] + acc[i][j];
            }
        }
        if (tc == 0) {
            if (tid < TT) red[tid] = 0.f;
            __syncthreads();
            atomicAdd(&red[ms+0], csum[0]); atomicAdd(&red[ms+1], csum[1]);
            atomicAdd(&red[ms+2], csum[2]); atomicAdd(&red[ms+3], csum[3]);
            __syncthreads();
            if (tid < TT)
                o_nb0[bb*HH + m0 + tid] = df * sb0[bb*HH + m0 + tid] + red[tid];
        }
    } else if (bid < 240) {   // out: 768 dots K=384
        int w = (bid - 144)*8 + (tid >> 5);
        int b2 = w / CC, c = w % CC;
        float s = warpdot4((const float4*)(g_pred + b2*CC),
                           (const float4*)(Wo + (size_t)c*CC), CC/4) + bo[c];
        if ((tid & 31) == 0) o_out[w] = s;
    }
}

// ============================================================================
extern "C" void kernel_launch(void* const* d_in, const int* in_sizes, int n_in,
                              void* d_out, int out_size) {
    const float* x   = (const float*)d_in[0];
    const float* Wq  = (const float*)d_in[1];
    const float* bq  = (const float*)d_in[2];
    const float* Wk  = (const float*)d_in[3];
    const float* bk  = (const float*)d_in[4];
    const float* Wv  = (const float*)d_in[5];
    const float* bv  = (const float*)d_in[6];
    const float* Wo  = (const float*)d_in[7];
    const float* bo  = (const float*)d_in[8];
    const float* iq  = (const float*)d_in[9];
    const float* sW0 = (const float*)d_in[10];
    const float* sb0 = (const float*)d_in[11];
    const float* sW1 = (const float*)d_in[12];
    const float* sb1 = (const float*)d_in[13];

    float* out   = (float*)d_out;
    float* o_out = out;
    float* o_nw0 = o_out + BB*CC;
    float* o_nb0 = o_nw0 + (size_t)BB*HH*CC;
    float* o_nw1 = o_nb0 + BB*HH;
    float* o_nb1 = o_nw1 + (size_t)BB*CC*HH;

    fused<<<NB, 256>>>(x, Wq, bq, Wk, bk, Wv, bv, Wo, bo, iq, sW0, sb0, sW1, sb1,
                       o_out, o_nw0, o_nb0, o_nw1, o_nb1);
}

// round 16
// speedup vs baseline: 1.5375x; 1.1261x over previous
#include <cuda_runtime.h>
#include <cuda_bf16.h>
#include <math.h>

#define BB 2
#define TT 64
#define CC 384
#define HH 768
#define BKt 16
#define LDA_S 68
#define NB 288
#define KVN (128*768)    // one k||v part buffer: [B*T=128][768]

// ---------------- scratch (device globals) ----------------
#define N_KV (BB*TT*CC)   // 49152
#define N_H  (BB*TT*HH)   // 98304
__device__ float g_kvp[6*KVN];  // splitK parts of k||v (plain stores, no init)
__device__ float g_k[N_KV];     // finalized k (S2 spares)
__device__ float g_v[N_KV];     // finalized v (S2 spares)
__device__ float g_dp[N_KV];    // holds p; consumers do p - v
__device__ float g_h1[N_H];     // layer-1 pre-activation (bias included)
__device__ float g_ds[N_H];     // (p-v) @ W1
__device__ float g_q[CC];
__device__ float g_h[BB*HH];
__device__ float g_pred[BB*CC];
__device__ unsigned g_bar[8];   // monotonic tickets, never reset

__device__ __forceinline__ float silu_f(float x) {
    float s = 1.f / (1.f + expf(-x)); return x * s;
}
__device__ __forceinline__ float gfac_f(float x) {
    float s = 1.f / (1.f + expf(-x)); return s * (1.f + x * (1.f - s));
}

__device__ __forceinline__ void grid_bar(int which) {
    __syncthreads();
    if (threadIdx.x == 0) {
        unsigned* p = &g_bar[which];
        unsigned ticket;
        asm volatile("atom.release.gpu.global.add.u32 %0, [%1], 1;"
                     : "=r"(ticket) : "l"(p) : "memory");
        unsigned target = ticket - (ticket % NB) + NB;
        unsigned cur;
        do {
            __nanosleep(32);
            asm volatile("ld.acquire.gpu.global.u32 %0, [%1];"
                         : "=r"(cur) : "l"(p) : "memory");
        } while ((int)(cur - target) < 0);
    }
    __syncthreads();
}

__device__ __forceinline__ float warpdot4(const float4* a, const float4* b, int n4) {
    float s = 0.f;
    for (int i = (threadIdx.x & 31); i < n4; i += 32) {
        float4 x = a[i], y = b[i];
        s += x.x*y.x + x.y*y.y + x.z*y.z + x.w*y.w;
    }
    #pragma unroll
    for (int o = 16; o; o >>= 1) s += __shfl_xor_sync(0xFFFFFFFFu, s, o);
    return s;
}

// ---- packed-f32x2 GEMM core: acc pairs rows (2i,2i+1) per 64-bit lane ----
// accp[p][j] = f32x2 accumulator for rows (tm*4+2p, tm*4+2p+1), col tn*4+j.
__device__ __forceinline__ void core16(const float (*As)[LDA_S], const float (*Bs)[LDA_S],
                                       unsigned long long (&accp)[2][4], int tm, int tn) {
    #pragma unroll
    for (int kk = 0; kk < BKt; ++kk) {
        ulonglong2 a2 = *(const ulonglong2*)&As[kk][tm*4];   // LDS.128: rows as 2 f32x2
        float4 b4 = *(const float4*)&Bs[kk][tn*4];
        unsigned long long b0, b1, b2, b3;
        asm("mov.b64 %0, {%1, %1};" : "=l"(b0) : "f"(b4.x));
        asm("mov.b64 %0, {%1, %1};" : "=l"(b1) : "f"(b4.y));
        asm("mov.b64 %0, {%1, %1};" : "=l"(b2) : "f"(b4.z));
        asm("mov.b64 %0, {%1, %1};" : "=l"(b3) : "f"(b4.w));
        asm("fma.rn.f32x2 %0, %1, %2, %0;" : "+l"(accp[0][0]) : "l"(a2.x), "l"(b0));
        asm("fma.rn.f32x2 %0, %1, %2, %0;" : "+l"(accp[1][0]) : "l"(a2.y), "l"(b0));
        asm("fma.rn.f32x2 %0, %1, %2, %0;" : "+l"(accp[0][1]) : "l"(a2.x), "l"(b1));
        asm("fma.rn.f32x2 %0, %1, %2, %0;" : "+l"(accp[1][1]) : "l"(a2.y), "l"(b1));
        asm("fma.rn.f32x2 %0, %1, %2, %0;" : "+l"(accp[0][2]) : "l"(a2.x), "l"(b2));
        asm("fma.rn.f32x2 %0, %1, %2, %0;" : "+l"(accp[1][2]) : "l"(a2.y), "l"(b2));
        asm("fma.rn.f32x2 %0, %1, %2, %0;" : "+l"(accp[0][3]) : "l"(a2.x), "l"(b3));
        asm("fma.rn.f32x2 %0, %1, %2, %0;" : "+l"(accp[1][3]) : "l"(a2.y), "l"(b3));
    }
}

__device__ __forceinline__ void unpack_acc(const unsigned long long (&accp)[2][4],
                                           float (&acc)[4][4]) {
    #pragma unroll
    for (int p = 0; p < 2; ++p)
        #pragma unroll
        for (int j = 0; j < 4; ++j) {
            float lo, hi;
            asm("mov.b64 {%0, %1}, %2;" : "=f"(lo), "=f"(hi) : "l"(accp[p][j]));
            acc[2*p+0][j] = lo;
            acc[2*p+1][j] = hi;
        }
}

__device__ __forceinline__ void sts4(float (*S)[LDA_S], int r, int ks, float4 v) {
    S[ks+0][r] = v.x; S[ks+1][r] = v.y; S[ks+2][r] = v.z; S[ks+3][r] = v.w;
}

// sum the 6 k||v parts at a flat [row*768+col] offset
__device__ __forceinline__ float4 sum_parts(size_t off) {
    float4 s = make_float4(0.f, 0.f, 0.f, 0.f);
    #pragma unroll
    for (int p = 0; p < 6; ++p) {
        float4 t = *(const float4*)&g_kvp[(size_t)p*KVN + off];
        s.x += t.x; s.y += t.y; s.z += t.z; s.w += t.w;
    }
    return s;
}

// ============================================================================
__global__ void __launch_bounds__(256, 2)
fused(const float* __restrict__ x,   const float* __restrict__ Wq,
      const float* __restrict__ bq,  const float* __restrict__ Wk,
      const float* __restrict__ bk,  const float* __restrict__ Wv,
      const float* __restrict__ bv,  const float* __restrict__ Wo,
      const float* __restrict__ bo,  const float* __restrict__ iq,
      const float* __restrict__ sW0, const float* __restrict__ sb0,
      const float* __restrict__ sW1, const float* __restrict__ sb1,
      float* __restrict__ o_out, float* __restrict__ o_nw0,
      float* __restrict__ o_nb0, float* __restrict__ o_nw1,
      float* __restrict__ o_nb1)
{
    __shared__ float As[2][BKt][LDA_S];
    __shared__ float Bs[2][BKt][LDA_S];
    __shared__ float red[TT];
    __shared__ float coeff_s[TT];

    const int bid = blockIdx.x, tid = threadIdx.x;
    const int r  = tid >> 2, ks = (tid & 3) << 2;   // transpose-load role
    const int tm = tid & 15, tn = tid >> 4;          // micro-tile role

    // ======== S1: kv GEMM parts (144) | inits + q (144) ========
    if (bid < 144) {
        int kc = bid % 6, tile = bid / 6;
        int tr = tile / 12, tc = tile % 12;
        int m0 = tr*64, n0 = tc*64, k0 = kc*64;
        const float* Wn = (n0 < CC) ? Wk + (size_t)n0*CC : Wv + (size_t)(n0-CC)*CC;
        const float* pa = x  + (size_t)(m0 + r)*CC + k0 + ks;
        const float* pb = Wn + (size_t)r*CC       + k0 + ks;
        float4 ra = *(const float4*)pa, rb = *(const float4*)pb;
        sts4(As[0], r, ks, ra); sts4(Bs[0], r, ks, rb);
        __syncthreads();
        unsigned long long accp[2][4] = {};
        #pragma unroll
        for (int kt = 0; kt < 4; ++kt) {
            if (kt < 3) { ra = *(const float4*)(pa + (kt+1)*BKt);
                          rb = *(const float4*)(pb + (kt+1)*BKt); }
            core16(As[kt&1], Bs[kt&1], accp, tm, tn);
            if (kt < 3) { sts4(As[(kt+1)&1], r, ks, ra); sts4(Bs[(kt+1)&1], r, ks, rb); }
            __syncthreads();
        }
        float acc[4][4]; unpack_acc(accp, acc);
        float4 badd = make_float4(0.f, 0.f, 0.f, 0.f);
        if (kc == 0) {
            int c = n0 + tn*4;
            const float* bsrc = (c < CC) ? bk + c : bv + (c - CC);
            badd = make_float4(bsrc[0], bsrc[1], bsrc[2], bsrc[3]);
        }
        float* dst = g_kvp + (size_t)kc*KVN;
        #pragma unroll
        for (int i = 0; i < 4; ++i) {
            int m = m0 + tm*4 + i;
            *(float4*)&dst[(size_t)m*768 + n0 + tn*4] =
                make_float4(acc[i][0]+badd.x, acc[i][1]+badd.y,
                            acc[i][2]+badd.z, acc[i][3]+badd.w);
        }
    } else {
        int gt = (bid - 144)*256 + tid;
        for (int i = gt; i < N_H; i += 144*256) {
            g_h1[i] = sb0[(i/(TT*HH))*HH + (i % HH)];
            g_ds[i] = 0.f;
        }
        for (int i = gt; i < N_KV; i += 144*256)
            g_dp[i] = sb1[(i/(TT*CC))*CC + (i % CC)];
        if (bid >= 240) {   // q: 384 dots, K=384
            int w = (bid - 240)*8 + (tid >> 5);
            float s = warpdot4((const float4*)iq, (const float4*)(Wq + (size_t)w*CC), CC/4);
            if ((tid & 31) == 0) g_q[w] = s + bq[w];
        }
    }
    grid_bar(0);

    // ======== S2: h1pre GEMM from parts (144) | h dots + finalize k,v (144) ========
    if (bid < 144) {
        int kc = bid % 6, tile = bid / 6;
        int bb = tile / 12, tc = tile % 12;
        int n0 = tc*64, k0 = kc*64;
        size_t abase = (size_t)(bb*64 + r)*768 + k0 + ks;   // k cols 0..383
        const float* pb = sW0 + (size_t)(bb*HH + n0 + r)*CC + k0 + ks;
        float4 ra = sum_parts(abase);
        float4 rb = *(const float4*)pb;
        sts4(As[0], r, ks, ra); sts4(Bs[0], r, ks, rb);
        __syncthreads();
        unsigned long long accp[2][4] = {};
        #pragma unroll
        for (int kt = 0; kt < 4; ++kt) {
            if (kt < 3) { ra = sum_parts(abase + (kt+1)*BKt);
                          rb = *(const float4*)(pb + (kt+1)*BKt); }
            core16(As[kt&1], Bs[kt&1], accp, tm, tn);
            if (kt < 3) { sts4(As[(kt+1)&1], r, ks, ra); sts4(Bs[(kt+1)&1], r, ks, rb); }
            __syncthreads();
        }
        float acc[4][4]; unpack_acc(accp, acc);
        #pragma unroll
        for (int i = 0; i < 4; ++i) {
            int m = tm*4 + i;
            #pragma unroll
            for (int j = 0; j < 4; ++j)
                atomicAdd(&g_h1[(size_t)(bb*TT + m)*HH + n0 + tn*4 + j], acc[i][j]);
        }
    } else {
        // finalize k and v for S4/S5 consumers
        int gt = (bid - 144)*256 + tid;
        for (int i4 = gt; i4 < N_KV/4; i4 += 144*256) {    // 12288
            int row = i4 / 96, c4 = (i4 % 96) * 4;
            size_t base = (size_t)row*768 + c4;
            *(float4*)&g_k[(size_t)row*CC + c4] = sum_parts(base);
            *(float4*)&g_v[(size_t)row*CC + c4] = sum_parts(base + 384);
        }
        // h: 1536 dots K=384
        for (int w = (bid - 144)*8 + (tid >> 5); w < BB*HH; w += 144*8) {
            float s = warpdot4((const float4*)g_q, (const float4*)(sW0 + (size_t)w*CC),
                               CC/4) + sb0[w];
            if ((tid & 31) == 0) g_h[w] = silu_f(s);
        }
    }
    grid_bar(1);

    // ======== S3: p GEMM, A=silu(h1), splitK12 (144) | pred dots (144) ========
    if (bid < 144) {
        int kc = bid % 12, tile = bid / 12;
        int bb = tile / 6, tc = tile % 6;
        int n0 = tc*64, k0 = kc*64;
        const float* pa = g_h1 + (size_t)(bb*TT + r)*HH + k0 + ks;
        const float* pb = sW1 + (size_t)(bb*CC + n0 + r)*HH + k0 + ks;
        float4 ra = *(const float4*)pa, rb = *(const float4*)pb;
        sts4(As[0], r, ks, make_float4(silu_f(ra.x), silu_f(ra.y), silu_f(ra.z), silu_f(ra.w)));
        sts4(Bs[0], r, ks, rb);
        __syncthreads();
        unsigned long long accp[2][4] = {};
        #pragma unroll
        for (int kt = 0; kt < 4; ++kt) {
            if (kt < 3) { ra = *(const float4*)(pa + (kt+1)*BKt);
                          rb = *(const float4*)(pb + (kt+1)*BKt); }
            core16(As[kt&1], Bs[kt&1], accp, tm, tn);
            if (kt < 3) {
                sts4(As[(kt+1)&1], r, ks,
                     make_float4(silu_f(ra.x), silu_f(ra.y), silu_f(ra.z), silu_f(ra.w)));
                sts4(Bs[(kt+1)&1], r, ks, rb);
            }
            __syncthreads();
        }
        float acc[4][4]; unpack_acc(accp, acc);
        #pragma unroll
        for (int i = 0; i < 4; ++i) {
            int m = tm*4 + i;
            #pragma unroll
            for (int j = 0; j < 4; ++j)
                atomicAdd(&g_dp[(size_t)(bb*TT + m)*CC + n0 + tn*4 + j], acc[i][j]);
        }
    } else {            // pred: 768 dots K=768
        int w = (bid - 144)*8 + (tid >> 5);
        if (w < BB*CC) {
            int b = w / CC;
            float s = warpdot4((const float4*)(g_h + b*HH),
                               (const float4*)(sW1 + (size_t)w*HH), HH/4) + sb1[w];
            if ((tid & 31) == 0) g_pred[w] = s;
        }
    }
    grid_bar(2);

    // ======== S4: ds GEMM = (p - v) @ sW1, all 288, splitK12; out dots appended ========
    {
        int kc = bid % 12, tile = bid / 12;
        int bb = tile / 12, tc = tile % 12;
        int n0 = tc*64, k0 = kc*32;
        int kkb = tid >> 4, cs = (tid & 15) << 2;
        const float* pap = g_dp + (size_t)(bb*TT + r)*CC + k0 + ks;
        const float* pav = g_v  + (size_t)(bb*TT + r)*CC + k0 + ks;
        const float* pb  = sW1 + (size_t)(bb*CC + k0 + kkb)*HH + n0 + cs;
        float4 rp = *(const float4*)pap, rv = *(const float4*)pav;
        float4 rb = *(const float4*)pb;
        sts4(As[0], r, ks, make_float4(rp.x - rv.x, rp.y - rv.y, rp.z - rv.z, rp.w - rv.w));
        *(float4*)&Bs[0][kkb][cs] = rb;
        __syncthreads();
        unsigned long long accp[2][4] = {};
        #pragma unroll
        for (int kt = 0; kt < 2; ++kt) {
            if (kt < 1) { rp = *(const float4*)(pap + BKt);
                          rv = *(const float4*)(pav + BKt);
                          rb = *(const float4*)(pb + (size_t)BKt*HH); }
            core16(As[kt&1], Bs[kt&1], accp, tm, tn);
            if (kt < 1) {
                sts4(As[1], r, ks, make_float4(rp.x - rv.x, rp.y - rv.y, rp.z - rv.z, rp.w - rv.w));
                *(float4*)&Bs[1][kkb][cs] = rb;
            }
            __syncthreads();
        }
        float acc[4][4]; unpack_acc(accp, acc);
        #pragma unroll
        for (int i = 0; i < 4; ++i) {
            int m = tm*4 + i;
            #pragma unroll
            for (int j = 0; j < 4; ++j)
                atomicAdd(&g_ds[(size_t)(bb*TT + m)*HH + n0 + tn*4 + j], acc[i][j]);
        }
        // out dots overlap the REDG drain: 768 dots K=384 on blocks 0-95
        if (bid < 96) {
            int w = bid*8 + (tid >> 5);
            int b = w / CC, c = w % CC;
            float s = warpdot4((const float4*)(g_pred + b*CC),
                               (const float4*)(Wo + (size_t)c*CC), CC/4) + bo[c];
            if ((tid & 31) == 0) o_out[w] = s;
        }
    }
    grid_bar(3);

    // ======== S5: nW0 (144) + nW1 (144), biases folded into tc==0 tiles ========
    {
        if (tid < TT) {
            double d = 0.999, rr_ = 0.9 / 0.999;
            double csm = pow(d, (double)(TT-1-tid)) * (pow(rr_, (double)(TT-tid)) - 1.0)
                         / (rr_ - 1.0);
            coeff_s[tid] = (float)(-0.01 * 0.1 * csm);
        }
        __syncthreads();
        const float df = (float)pow(0.999, (double)TT);

        bool is0 = bid < 144;
        int tile = is0 ? bid : bid - 144;
        int bb = tile / 72, rr = tile % 72;
        int tr = is0 ? rr/6 : rr/12;
        int tc = is0 ? rr%6 : rr%12;
        int m0 = tr*64, n0 = tc*64;
        int kk = tid >> 4, ms = (tid & 15) << 2;
        float4 r1, r2, r3;
        float csum[4] = {0.f, 0.f, 0.f, 0.f};

        #define LD_SLAB(kt) do {                                                   \
            int t_ = (kt)*BKt + kk;                                                \
            if (is0) {                                                             \
                size_t ia = (size_t)(bb*TT + t_)*HH + m0 + ms;                     \
                r1 = *(const float4*)&g_ds[ia];                                    \
                r2 = *(const float4*)&g_h1[ia];                                    \
                r3 = *(const float4*)&g_k[(size_t)(bb*TT + t_)*CC + n0 + ms];      \
            } else {                                                               \
                size_t ia = (size_t)(bb*TT + t_)*CC + m0 + ms;                     \
                float4 pp = *(const float4*)&g_dp[ia];                             \
                float4 vv = *(const float4*)&g_v[ia];                              \
                r1 = make_float4(pp.x - vv.x, pp.y - vv.y, pp.z - vv.z, pp.w - vv.w);\
                r2 = *(const float4*)&g_h1[(size_t)(bb*TT + t_)*HH + n0 + ms];     \
            }                                                                      \
        } while (0)
        #define ST_SLAB(buf, kt) do {                                              \
            int t_ = (kt)*BKt + kk;                                                \
            float cf = coeff_s[t_];                                                \
            float a0, a1, a2, a3;                                                  \
            if (is0) {                                                             \
                a0 = cf * r1.x * gfac_f(r2.x); a1 = cf * r1.y * gfac_f(r2.y);      \
                a2 = cf * r1.z * gfac_f(r2.z); a3 = cf * r1.w * gfac_f(r2.w);      \
                *(float4*)&Bs[buf][kk][ms] = r3;                                   \
            } else {                                                               \
                a0 = cf * r1.x; a1 = cf * r1.y; a2 = cf * r1.z; a3 = cf * r1.w;    \
                Bs[buf][kk][ms+0] = silu_f(r2.x); Bs[buf][kk][ms+1] = silu_f(r2.y);\
                Bs[buf][kk][ms+2] = silu_f(r2.z); Bs[buf][kk][ms+3] = silu_f(r2.w);\
            }                                                                      \
            As[buf][kk][ms+0] = a0; As[buf][kk][ms+1] = a1;                        \
            As[buf][kk][ms+2] = a2; As[buf][kk][ms+3] = a3;                        \
            csum[0] += a0; csum[1] += a1; csum[2] += a2; csum[3] += a3;            \
        } while (0)

        LD_SLAB(0); ST_SLAB(0, 0);
        __syncthreads();
        unsigned long long accp[2][4] = {};
        #pragma unroll
        for (int kt = 0; kt < 4; ++kt) {
            if (kt < 3) LD_SLAB(kt+1);
            core16(As[kt&1], Bs[kt&1], accp, tm, tn);
            if (kt < 3) ST_SLAB((kt+1)&1, kt+1);
            __syncthreads();
        }
        float acc[4][4]; unpack_acc(accp, acc);
        if (is0) {
            #pragma unroll
            for (int i = 0; i < 4; ++i) {
                int h = m0 + tm*4 + i;
                #pragma unroll
                for (int j = 0; j < 4; ++j) {
                    size_t idx = (size_t)(bb*HH + h)*CC + n0 + tn*4 + j;
                    o_nw0[idx] = df * sW0[idx] + acc[i][j];
                }
            }
        } else {
            #pragma unroll
            for (int i = 0; i < 4; ++i) {
                int c = m0 + tm*4 + i;
                #pragma unroll
                for (int j = 0; j < 4; ++j) {
                    size_t idx = (size_t)(bb*CC + c)*HH + n0 + tn*4 + j;
                    o_nw1[idx] = df * sW1[idx] + acc[i][j];
                }
            }
        }
        if (tc == 0) {   // fold biases: column sums of A
            if (tid < TT) red[tid] = 0.f;
            __syncthreads();
            atomicAdd(&red[ms+0], csum[0]); atomicAdd(&red[ms+1], csum[1]);
            atomicAdd(&red[ms+2], csum[2]); atomicAdd(&red[ms+3], csum[3]);
            __syncthreads();
            if (tid < TT) {
                if (is0) o_nb0[bb*HH + m0 + tid] = df * sb0[bb*HH + m0 + tid] + red[tid];
                else     o_nb1[bb*CC + m0 + tid] = df * sb1[bb*CC + m0 + tid] + red[tid];
            }
        }
    }
}

// ============================================================================
extern "C" void kernel_launch(void* const* d_in, const int* in_sizes, int n_in,
                              void* d_out, int out_size) {
    const float* x   = (const float*)d_in[0];
    const float* Wq  = (const float*)d_in[1];
    const float* bq  = (const float*)d_in[2];
    const float* Wk  = (const float*)d_in[3];
    const float* bk  = (const float*)d_in[4];
    const float* Wv  = (const float*)d_in[5];
    const float* bv  = (const float*)d_in[6];
    const float* Wo  = (const float*)d_in[7];
    const float* bo  = (const float*)d_in[8];
    const float* iq  = (const float*)d_in[9];
    const float* sW0 = (const float*)d_in[10];
    const float* sb0 = (const float*)d_in[11];
    const float* sW1 = (const float*)d_in[12];
    const float* sb1 = (const float*)d_in[13];

    float* out   = (float*)d_out;
    float* o_out = out;
    float* o_nw0 = o_out + BB*CC;
    float* o_nb0 = o_nw0 + (size_t)BB*HH*CC;
    float* o_nw1 = o_nb0 + BB*HH;
    float* o_nb1 = o_nw1 + (size_t)BB*CC*HH;

    fused<<<NB, 256>>>(x, Wq, bq, Wk, bk, Wv, bv, Wo, bo, iq, sW0, sb0, sW1, sb1,
                       o_out, o_nw0, o_nb0, o_nw1, o_nb1);
}